// round 1
// baseline (speedup 1.0000x reference)
#include <cuda_runtime.h>
#include <math.h>

#define NB 4
#define NT 4096
#define NC 512
#define NH 64
#define NM (NB*NT)            // 16384 rows

// scratch for k, q, v projections: [3][B*T][H]  (device global = sanctioned scratch)
__device__ float g_kqv[3][(size_t)NM * NH];

// ---------------------------------------------------------------------------
// Kernel 1: fused QKV projection.  out[w] = x @ W_w, q pre-scaled by C^-0.5.
// grid (256, 3): blockIdx.x = 64-row tile of M=16384, blockIdx.y = which W.
// block 256 threads = 16x16, each computes a 4x4 micro-tile.
// ---------------------------------------------------------------------------
__global__ __launch_bounds__(256) void proj_kernel(
    const float* __restrict__ x,
    const float* __restrict__ Wk,
    const float* __restrict__ Wq,
    const float* __restrict__ Wv)
{
    __shared__ float As[64 * 32];   // x tile   [m][k]
    __shared__ float Bs[32 * 64];   // W tile   [k][n]

    const int tid = threadIdx.x;
    const int ty  = tid >> 4;       // 0..15
    const int tx  = tid & 15;       // 0..15
    const int m0  = blockIdx.x * 64;
    const int w   = blockIdx.y;     // 0=k, 1=q, 2=v
    const float* __restrict__ W = (w == 0) ? Wk : (w == 1) ? Wq : Wv;

    float acc[4][4];
#pragma unroll
    for (int i = 0; i < 4; i++)
#pragma unroll
        for (int j = 0; j < 4; j++) acc[i][j] = 0.f;

    for (int k0 = 0; k0 < NC; k0 += 32) {
        // load A: 64x32 floats = 512 float4, 2 per thread
#pragma unroll
        for (int u = 0; u < 2; u++) {
            int f = tid + u * 256;
            int r = f >> 3, c = f & 7;
            *(float4*)&As[r * 32 + c * 4] =
                *(const float4*)&x[(size_t)(m0 + r) * NC + k0 + c * 4];
        }
        // load B: 32x64 floats = 512 float4, 2 per thread
#pragma unroll
        for (int u = 0; u < 2; u++) {
            int f = tid + u * 256;
            int r = f >> 4, c = f & 15;
            *(float4*)&Bs[r * 64 + c * 4] =
                *(const float4*)&W[(size_t)(k0 + r) * NH + c * 4];
        }
        __syncthreads();

#pragma unroll
        for (int kk = 0; kk < 32; kk += 4) {
            float av[4][4], bv[4][4];
#pragma unroll
            for (int i = 0; i < 4; i++) {
                float4 t4 = *(float4*)&As[(ty * 4 + i) * 32 + kk];
                av[i][0] = t4.x; av[i][1] = t4.y; av[i][2] = t4.z; av[i][3] = t4.w;
            }
#pragma unroll
            for (int t = 0; t < 4; t++) {
                float4 t4 = *(float4*)&Bs[(kk + t) * 64 + tx * 4];
                bv[t][0] = t4.x; bv[t][1] = t4.y; bv[t][2] = t4.z; bv[t][3] = t4.w;
            }
#pragma unroll
            for (int i = 0; i < 4; i++)
#pragma unroll
                for (int j = 0; j < 4; j++)
#pragma unroll
                    for (int t = 0; t < 4; t++)
                        acc[i][j] = fmaf(av[i][t], bv[t][j], acc[i][j]);
        }
        __syncthreads();
    }

    const float scale = (w == 1) ? 0.044194173824159216f : 1.0f;  // 512^-0.5 folded into q
    float* __restrict__ outb = g_kqv[w];
#pragma unroll
    for (int i = 0; i < 4; i++) {
        float4 o4 = make_float4(acc[i][0] * scale, acc[i][1] * scale,
                                acc[i][2] * scale, acc[i][3] * scale);
        *(float4*)&outb[(size_t)(m0 + ty * 4 + i) * NH + tx * 4] = o4;
    }
}

// ---------------------------------------------------------------------------
// Kernel 2: flash attention (online softmax), causal.
// One CTA handles two q-tiles (i, 63-i) -> constant 65 tile-pairs per CTA.
// 256 threads = 16x16; thread owns rows ty*4+i, columns tx+16*j (strided
// column ownership keeps hot-loop scalar LDS conflict-free with stride-65 Ks).
// ---------------------------------------------------------------------------
#define QS_OFF 0
#define KS_OFF 4096            // Ks: [c][k] stride 65  -> 4160 floats
#define VS_OFF (4096 + 4160)   // Vs: [s][h] stride 64  -> 4096 floats
#define PS_OFF (4096 + 4160 + 4096)
#define SMEM_FLOATS (4096 + 4160 + 4096 + 4096)   // 16448 floats = 65792 B

__device__ __forceinline__ void process_qtile(
    int b, int qt, float* Qs, float* Ks, float* Vs, float* Ps,
    float* __restrict__ out, int tid, int ty, int tx)
{
    // load Q tile (already scaled): 64x64 floats = 1024 float4, 4/thread
    const float* __restrict__ qg = g_kqv[1] + ((size_t)b * NT + (size_t)qt * 64) * NH;
#pragma unroll
    for (int u = 0; u < 4; u++) {
        int f = tid + u * 256;
        int r = f >> 4, c4 = f & 15;
        *(float4*)&Qs[r * 64 + c4 * 4] = *(const float4*)&qg[r * NH + c4 * 4];
    }

    float m[4], l[4], o[4][4];
#pragma unroll
    for (int i = 0; i < 4; i++) {
        m[i] = -1e30f; l[i] = 0.f;
#pragma unroll
        for (int j = 0; j < 4; j++) o[i][j] = 0.f;
    }

    for (int kt = 0; kt <= qt; kt++) {
        const float* __restrict__ kg = g_kqv[0] + ((size_t)b * NT + (size_t)kt * 64) * NH;
        const float* __restrict__ vg = g_kqv[2] + ((size_t)b * NT + (size_t)kt * 64) * NH;
#pragma unroll
        for (int u = 0; u < 4; u++) {
            int f = tid + u * 256;
            int r = f >> 4, c4 = f & 15;
            float4 kv4 = *(const float4*)&kg[r * NH + c4 * 4];
            Ks[r * 65 + c4 * 4 + 0] = kv4.x;
            Ks[r * 65 + c4 * 4 + 1] = kv4.y;
            Ks[r * 65 + c4 * 4 + 2] = kv4.z;
            Ks[r * 65 + c4 * 4 + 3] = kv4.w;
            *(float4*)&Vs[r * 64 + c4 * 4] = *(const float4*)&vg[r * NH + c4 * 4];
        }
        __syncthreads();

        // S = Q K^T  (q already scaled)
        float s[4][4];
#pragma unroll
        for (int i = 0; i < 4; i++)
#pragma unroll
            for (int j = 0; j < 4; j++) s[i][j] = 0.f;

#pragma unroll
        for (int kk = 0; kk < 64; kk += 4) {
            float qv[4][4], kv[4][4];
#pragma unroll
            for (int i = 0; i < 4; i++) {
                float4 t4 = *(float4*)&Qs[(ty * 4 + i) * 64 + kk];
                qv[i][0] = t4.x; qv[i][1] = t4.y; qv[i][2] = t4.z; qv[i][3] = t4.w;
            }
#pragma unroll
            for (int j = 0; j < 4; j++)
#pragma unroll
                for (int t = 0; t < 4; t++)
                    kv[j][t] = Ks[(tx + 16 * j) * 65 + kk + t];
#pragma unroll
            for (int i = 0; i < 4; i++)
#pragma unroll
                for (int j = 0; j < 4; j++)
#pragma unroll
                    for (int t = 0; t < 4; t++)
                        s[i][j] = fmaf(qv[i][t], kv[j][t], s[i][j]);
        }

        if (kt == qt) {   // causal mask inside diagonal tile
#pragma unroll
            for (int i = 0; i < 4; i++)
#pragma unroll
                for (int j = 0; j < 4; j++)
                    if ((tx + 16 * j) > (ty * 4 + i)) s[i][j] = -1e30f;
        }

        // online softmax update; lanes with same ty form a 16-lane shfl group
#pragma unroll
        for (int i = 0; i < 4; i++) {
            float rm = fmaxf(fmaxf(s[i][0], s[i][1]), fmaxf(s[i][2], s[i][3]));
            rm = fmaxf(rm, __shfl_xor_sync(0xffffffffu, rm, 8));
            rm = fmaxf(rm, __shfl_xor_sync(0xffffffffu, rm, 4));
            rm = fmaxf(rm, __shfl_xor_sync(0xffffffffu, rm, 2));
            rm = fmaxf(rm, __shfl_xor_sync(0xffffffffu, rm, 1));
            float mn   = fmaxf(m[i], rm);
            float corr = __expf(m[i] - mn);
            float p0 = __expf(s[i][0] - mn);
            float p1 = __expf(s[i][1] - mn);
            float p2 = __expf(s[i][2] - mn);
            float p3 = __expf(s[i][3] - mn);
            float rs = (p0 + p1) + (p2 + p3);
            rs += __shfl_xor_sync(0xffffffffu, rs, 8);
            rs += __shfl_xor_sync(0xffffffffu, rs, 4);
            rs += __shfl_xor_sync(0xffffffffu, rs, 2);
            rs += __shfl_xor_sync(0xffffffffu, rs, 1);
            l[i] = l[i] * corr + rs;
            m[i] = mn;
            o[i][0] *= corr; o[i][1] *= corr; o[i][2] *= corr; o[i][3] *= corr;
            int rb = (ty * 4 + i) * 64;
            Ps[rb + tx     ] = p0;
            Ps[rb + tx + 16] = p1;
            Ps[rb + tx + 32] = p2;
            Ps[rb + tx + 48] = p3;
        }
        __syncthreads();

        // O += P V
#pragma unroll
        for (int ss = 0; ss < 64; ss += 4) {
            float pv[4][4], vv[4][4];
#pragma unroll
            for (int i = 0; i < 4; i++) {
                float4 t4 = *(float4*)&Ps[(ty * 4 + i) * 64 + ss];
                pv[i][0] = t4.x; pv[i][1] = t4.y; pv[i][2] = t4.z; pv[i][3] = t4.w;
            }
#pragma unroll
            for (int t = 0; t < 4; t++)
#pragma unroll
                for (int j = 0; j < 4; j++)
                    vv[t][j] = Vs[(ss + t) * 64 + tx + 16 * j];
#pragma unroll
            for (int i = 0; i < 4; i++)
#pragma unroll
                for (int j = 0; j < 4; j++)
#pragma unroll
                    for (int t = 0; t < 4; t++)
                        o[i][j] = fmaf(pv[i][t], vv[t][j], o[i][j]);
        }
        __syncthreads();
    }

    // epilogue: normalize and store
#pragma unroll
    for (int i = 0; i < 4; i++) {
        float inv = 1.0f / l[i];
        size_t rb = ((size_t)b * NT + (size_t)qt * 64 + ty * 4 + i) * NH;
#pragma unroll
        for (int j = 0; j < 4; j++)
            out[rb + tx + 16 * j] = o[i][j] * inv;
    }
}

__global__ __launch_bounds__(256) void attn_kernel(float* __restrict__ out)
{
    extern __shared__ float sm[];
    float* Qs = sm + QS_OFF;
    float* Ks = sm + KS_OFF;
    float* Vs = sm + VS_OFF;
    float* Ps = sm + PS_OFF;

    const int tid = threadIdx.x;
    const int ty  = tid >> 4;
    const int tx  = tid & 15;
    const int pp  = blockIdx.x;   // 0..31
    const int b   = blockIdx.y;   // 0..3

    // balanced pairing: (pp) and (63-pp) -> every CTA does 65 tile-pairs
    process_qtile(b, 63 - pp, Qs, Ks, Vs, Ps, out, tid, ty, tx);
    process_qtile(b, pp,      Qs, Ks, Vs, Ps, out, tid, ty, tx);
}

// ---------------------------------------------------------------------------
extern "C" void kernel_launch(void* const* d_in, const int* in_sizes, int n_in,
                              void* d_out, int out_size)
{
    const float* x  = (const float*)d_in[0];
    const float* Wk = (const float*)d_in[1];
    const float* Wq = (const float*)d_in[2];
    const float* Wv = (const float*)d_in[3];
    float* out = (float*)d_out;

    cudaFuncSetAttribute(attn_kernel,
                         cudaFuncAttributeMaxDynamicSharedMemorySize,
                         SMEM_FLOATS * sizeof(float));

    proj_kernel<<<dim3(256, 3), 256>>>(x, Wk, Wq, Wv);
    attn_kernel<<<dim3(32, NB), 256, SMEM_FLOATS * sizeof(float)>>>(out);
}

// round 2
// speedup vs baseline: 1.0030x; 1.0030x over previous
#include <cuda_runtime.h>
#include <math.h>

#define NB 4
#define NT 4096
#define NC 512
#define NH 64
#define NM (NB*NT)            // 16384 rows

// scratch for k, q, v projections: [3][B*T][H]  (device global = sanctioned scratch)
__device__ float g_kqv[3][(size_t)NM * NH];

// ---------------------------------------------------------------------------
// Kernel 1: fused QKV projection.  out[w] = x @ W_w, q pre-scaled by C^-0.5.
// grid (256, 3): blockIdx.x = 64-row tile of M=16384, blockIdx.y = which W.
// block 256 threads = 16x16, each computes a 4x4 micro-tile.
// ---------------------------------------------------------------------------
__global__ __launch_bounds__(256) void proj_kernel(
    const float* __restrict__ x,
    const float* __restrict__ Wk,
    const float* __restrict__ Wq,
    const float* __restrict__ Wv)
{
    __shared__ float As[64 * 32];   // x tile   [m][k]
    __shared__ float Bs[32 * 64];   // W tile   [k][n]

    const int tid = threadIdx.x;
    const int ty  = tid >> 4;       // 0..15
    const int tx  = tid & 15;       // 0..15
    const int m0  = blockIdx.x * 64;
    const int w   = blockIdx.y;     // 0=k, 1=q, 2=v
    const float* __restrict__ W = (w == 0) ? Wk : (w == 1) ? Wq : Wv;

    float acc[4][4];
#pragma unroll
    for (int i = 0; i < 4; i++)
#pragma unroll
        for (int j = 0; j < 4; j++) acc[i][j] = 0.f;

    for (int k0 = 0; k0 < NC; k0 += 32) {
        // load A: 64x32 floats = 512 float4, 2 per thread
#pragma unroll
        for (int u = 0; u < 2; u++) {
            int f = tid + u * 256;
            int r = f >> 3, c = f & 7;
            *(float4*)&As[r * 32 + c * 4] =
                *(const float4*)&x[(size_t)(m0 + r) * NC + k0 + c * 4];
        }
        // load B: 32x64 floats = 512 float4, 2 per thread
#pragma unroll
        for (int u = 0; u < 2; u++) {
            int f = tid + u * 256;
            int r = f >> 4, c = f & 15;
            *(float4*)&Bs[r * 64 + c * 4] =
                *(const float4*)&W[(size_t)(k0 + r) * NH + c * 4];
        }
        __syncthreads();

#pragma unroll
        for (int kk = 0; kk < 32; kk += 4) {
            float av[4][4], bv[4][4];
#pragma unroll
            for (int i = 0; i < 4; i++) {
                float4 t4 = *(float4*)&As[(ty * 4 + i) * 32 + kk];
                av[i][0] = t4.x; av[i][1] = t4.y; av[i][2] = t4.z; av[i][3] = t4.w;
            }
#pragma unroll
            for (int t = 0; t < 4; t++) {
                float4 t4 = *(float4*)&Bs[(kk + t) * 64 + tx * 4];
                bv[t][0] = t4.x; bv[t][1] = t4.y; bv[t][2] = t4.z; bv[t][3] = t4.w;
            }
#pragma unroll
            for (int i = 0; i < 4; i++)
#pragma unroll
                for (int j = 0; j < 4; j++)
#pragma unroll
                    for (int t = 0; t < 4; t++)
                        acc[i][j] = fmaf(av[i][t], bv[t][j], acc[i][j]);
        }
        __syncthreads();
    }

    const float scale = (w == 1) ? 0.044194173824159216f : 1.0f;  // 512^-0.5 folded into q
    float* __restrict__ outb = g_kqv[w];
#pragma unroll
    for (int i = 0; i < 4; i++) {
        float4 o4 = make_float4(acc[i][0] * scale, acc[i][1] * scale,
                                acc[i][2] * scale, acc[i][3] * scale);
        *(float4*)&outb[(size_t)(m0 + ty * 4 + i) * NH + tx * 4] = o4;
    }
}

// ---------------------------------------------------------------------------
// Kernel 2: flash attention (online softmax), causal.
// One CTA handles two q-tiles (i, 63-i) -> constant 65 tile-pairs per CTA.
// 256 threads = 16x16; thread owns rows ty*4+i, columns tx+16*j (strided
// column ownership keeps hot-loop scalar LDS conflict-free with stride-65 Ks).
// ---------------------------------------------------------------------------
#define QS_OFF 0
#define KS_OFF 4096            // Ks: [c][k] stride 65  -> 4160 floats
#define VS_OFF (4096 + 4160)   // Vs: [s][h] stride 64  -> 4096 floats
#define PS_OFF (4096 + 4160 + 4096)
#define SMEM_FLOATS (4096 + 4160 + 4096 + 4096)   // 16448 floats = 65792 B

__device__ __forceinline__ void process_qtile(
    int b, int qt, float* Qs, float* Ks, float* Vs, float* Ps,
    float* __restrict__ out, int tid, int ty, int tx)
{
    // load Q tile (already scaled): 64x64 floats = 1024 float4, 4/thread
    const float* __restrict__ qg = g_kqv[1] + ((size_t)b * NT + (size_t)qt * 64) * NH;
#pragma unroll
    for (int u = 0; u < 4; u++) {
        int f = tid + u * 256;
        int r = f >> 4, c4 = f & 15;
        *(float4*)&Qs[r * 64 + c4 * 4] = *(const float4*)&qg[r * NH + c4 * 4];
    }

    float m[4], l[4], o[4][4];
#pragma unroll
    for (int i = 0; i < 4; i++) {
        m[i] = -1e30f; l[i] = 0.f;
#pragma unroll
        for (int j = 0; j < 4; j++) o[i][j] = 0.f;
    }

    for (int kt = 0; kt <= qt; kt++) {
        const float* __restrict__ kg = g_kqv[0] + ((size_t)b * NT + (size_t)kt * 64) * NH;
        const float* __restrict__ vg = g_kqv[2] + ((size_t)b * NT + (size_t)kt * 64) * NH;
#pragma unroll
        for (int u = 0; u < 4; u++) {
            int f = tid + u * 256;
            int r = f >> 4, c4 = f & 15;
            float4 kv4 = *(const float4*)&kg[r * NH + c4 * 4];
            Ks[r * 65 + c4 * 4 + 0] = kv4.x;
            Ks[r * 65 + c4 * 4 + 1] = kv4.y;
            Ks[r * 65 + c4 * 4 + 2] = kv4.z;
            Ks[r * 65 + c4 * 4 + 3] = kv4.w;
            *(float4*)&Vs[r * 64 + c4 * 4] = *(const float4*)&vg[r * NH + c4 * 4];
        }
        __syncthreads();

        // S = Q K^T  (q already scaled)
        float s[4][4];
#pragma unroll
        for (int i = 0; i < 4; i++)
#pragma unroll
            for (int j = 0; j < 4; j++) s[i][j] = 0.f;

#pragma unroll
        for (int kk = 0; kk < 64; kk += 4) {
            float qv[4][4], kv[4][4];
#pragma unroll
            for (int i = 0; i < 4; i++) {
                float4 t4 = *(float4*)&Qs[(ty * 4 + i) * 64 + kk];
                qv[i][0] = t4.x; qv[i][1] = t4.y; qv[i][2] = t4.z; qv[i][3] = t4.w;
            }
#pragma unroll
            for (int j = 0; j < 4; j++)
#pragma unroll
                for (int t = 0; t < 4; t++)
                    kv[j][t] = Ks[(tx + 16 * j) * 65 + kk + t];
#pragma unroll
            for (int i = 0; i < 4; i++)
#pragma unroll
                for (int j = 0; j < 4; j++)
#pragma unroll
                    for (int t = 0; t < 4; t++)
                        s[i][j] = fmaf(qv[i][t], kv[j][t], s[i][j]);
        }

        if (kt == qt) {   // causal mask inside diagonal tile
#pragma unroll
            for (int i = 0; i < 4; i++)
#pragma unroll
                for (int j = 0; j < 4; j++)
                    if ((tx + 16 * j) > (ty * 4 + i)) s[i][j] = -1e30f;
        }

        // online softmax update; lanes with same ty form a 16-lane shfl group
#pragma unroll
        for (int i = 0; i < 4; i++) {
            float rm = fmaxf(fmaxf(s[i][0], s[i][1]), fmaxf(s[i][2], s[i][3]));
            rm = fmaxf(rm, __shfl_xor_sync(0xffffffffu, rm, 8));
            rm = fmaxf(rm, __shfl_xor_sync(0xffffffffu, rm, 4));
            rm = fmaxf(rm, __shfl_xor_sync(0xffffffffu, rm, 2));
            rm = fmaxf(rm, __shfl_xor_sync(0xffffffffu, rm, 1));
            float mn   = fmaxf(m[i], rm);
            float corr = __expf(m[i] - mn);
            float p0 = __expf(s[i][0] - mn);
            float p1 = __expf(s[i][1] - mn);
            float p2 = __expf(s[i][2] - mn);
            float p3 = __expf(s[i][3] - mn);
            float rs = (p0 + p1) + (p2 + p3);
            rs += __shfl_xor_sync(0xffffffffu, rs, 8);
            rs += __shfl_xor_sync(0xffffffffu, rs, 4);
            rs += __shfl_xor_sync(0xffffffffu, rs, 2);
            rs += __shfl_xor_sync(0xffffffffu, rs, 1);
            l[i] = l[i] * corr + rs;
            m[i] = mn;
            o[i][0] *= corr; o[i][1] *= corr; o[i][2] *= corr; o[i][3] *= corr;
            int rb = (ty * 4 + i) * 64;
            Ps[rb + tx     ] = p0;
            Ps[rb + tx + 16] = p1;
            Ps[rb + tx + 32] = p2;
            Ps[rb + tx + 48] = p3;
        }
        __syncthreads();

        // O += P V
#pragma unroll
        for (int ss = 0; ss < 64; ss += 4) {
            float pv[4][4], vv[4][4];
#pragma unroll
            for (int i = 0; i < 4; i++) {
                float4 t4 = *(float4*)&Ps[(ty * 4 + i) * 64 + ss];
                pv[i][0] = t4.x; pv[i][1] = t4.y; pv[i][2] = t4.z; pv[i][3] = t4.w;
            }
#pragma unroll
            for (int t = 0; t < 4; t++)
#pragma unroll
                for (int j = 0; j < 4; j++)
                    vv[t][j] = Vs[(ss + t) * 64 + tx + 16 * j];
#pragma unroll
            for (int i = 0; i < 4; i++)
#pragma unroll
                for (int j = 0; j < 4; j++)
#pragma unroll
                    for (int t = 0; t < 4; t++)
                        o[i][j] = fmaf(pv[i][t], vv[t][j], o[i][j]);
        }
        __syncthreads();
    }

    // epilogue: normalize and store
#pragma unroll
    for (int i = 0; i < 4; i++) {
        float inv = 1.0f / l[i];
        size_t rb = ((size_t)b * NT + (size_t)qt * 64 + ty * 4 + i) * NH;
#pragma unroll
        for (int j = 0; j < 4; j++)
            out[rb + tx + 16 * j] = o[i][j] * inv;
    }
}

__global__ __launch_bounds__(256) void attn_kernel(float* __restrict__ out)
{
    extern __shared__ float sm[];
    float* Qs = sm + QS_OFF;
    float* Ks = sm + KS_OFF;
    float* Vs = sm + VS_OFF;
    float* Ps = sm + PS_OFF;

    const int tid = threadIdx.x;
    const int ty  = tid >> 4;
    const int tx  = tid & 15;
    const int pp  = blockIdx.x;   // 0..31
    const int b   = blockIdx.y;   // 0..3

    // balanced pairing: (pp) and (63-pp) -> every CTA does 65 tile-pairs
    process_qtile(b, 63 - pp, Qs, Ks, Vs, Ps, out, tid, ty, tx);
    process_qtile(b, pp,      Qs, Ks, Vs, Ps, out, tid, ty, tx);
}

// ---------------------------------------------------------------------------
extern "C" void kernel_launch(void* const* d_in, const int* in_sizes, int n_in,
                              void* d_out, int out_size)
{
    const float* x  = (const float*)d_in[0];
    const float* Wk = (const float*)d_in[1];
    const float* Wq = (const float*)d_in[2];
    const float* Wv = (const float*)d_in[3];
    float* out = (float*)d_out;

    cudaFuncSetAttribute(attn_kernel,
                         cudaFuncAttributeMaxDynamicSharedMemorySize,
                         SMEM_FLOATS * sizeof(float));

    proj_kernel<<<dim3(256, 3), 256>>>(x, Wk, Wq, Wv);
    attn_kernel<<<dim3(32, NB), 256, SMEM_FLOATS * sizeof(float)>>>(out);
}